// round 14
// baseline (speedup 1.0000x reference)
#include <cuda_runtime.h>
#include <cuda_bf16.h>
#include <cstdint>

// Problem dims
#define B     512
#define CIN   128
#define LIN   1024
#define KW    5
#define LOUT  1020
#define TT    1020
#define D1    128

#define XBSTR   (CIN*LIN)        // 131072
#define CBSTR   (CIN*LOUT)       // 130560 == TT*D1

// ---- scratch (device globals; no runtime allocation allowed) ----
__device__ __nv_bfloat16 g_seq_hi[(size_t)B * CBSTR];
__device__ __nv_bfloat16 g_seq_lo[(size_t)B * CBSTR];
__device__ float         g_xg   [(size_t)B * CBSTR];
// load-linear repacked fragments
__device__ unsigned      g_wpk_hi[4 * 40 * 32 * 8];   // [wm][slice][lane][8]
__device__ unsigned      g_wpk_lo[4 * 40 * 32 * 8];
__device__ unsigned      g_w1k_hi[2 * 8 * 8 * 64];    // [wn][kk][ni][lane*2+r]
__device__ unsigned      g_w1k_lo[2 * 8 * 8 * 64];

__device__ __forceinline__ float sigf(float x) {
    return __fdividef(1.0f, 1.0f + __expf(-x));
}
__device__ __forceinline__ float tanhfast(float x) {
    x = fminf(15.0f, fmaxf(-15.0f, x));
    float e = __expf(2.0f * x);
    return __fdividef(e - 1.0f, e + 1.0f);
}

__device__ __forceinline__ void split2(float v0, float v1, unsigned &uh, unsigned &ul) {
    __nv_bfloat16 h0 = __float2bfloat16_rn(v0);
    __nv_bfloat16 h1 = __float2bfloat16_rn(v1);
    float r0 = v0 - __bfloat162float(h0);
    float r1 = v1 - __bfloat162float(h1);
    __nv_bfloat162 ph; ph.x = h0; ph.y = h1;
    __nv_bfloat162 pl; pl.x = __float2bfloat16_rn(r0); pl.y = __float2bfloat16_rn(r1);
    uh = *(unsigned*)&ph;
    ul = *(unsigned*)&pl;
}

#define MMA_BF16(d, a0,a1,a2,a3, b0,b1)                                     \
    asm volatile("mma.sync.aligned.m16n8k16.row.col.f32.bf16.bf16.f32 "     \
        "{%0,%1,%2,%3},{%4,%5,%6,%7},{%8,%9},{%0,%1,%2,%3};"                \
        : "+f"(d[0]), "+f"(d[1]), "+f"(d[2]), "+f"(d[3])                    \
        : "r"(a0), "r"(a1), "r"(a2), "r"(a3), "r"(b0), "r"(b1))

// ---------------- Kernel 0: pack weights DIRECTLY into load-linear order ----------------
__global__ void prep_kernel(const float* __restrict__ conv_w, const float* __restrict__ Wih1) {
    int idx = blockIdx.x * 256 + threadIdx.x;
    if (idx < 4 * 40 * 32 * 8) {
        int q    = idx & 7;
        int lane = (idx >> 3) & 31;
        int s    = (idx >> 8) % 40;
        int wm   = idx / (40 * 256);
        int gid = lane >> 2, tig = lane & 3;
        int co = wm * 32 + gid + ((q >> 2) & 1) * 16 + (q & 1) * 8;
        int bw = s * 8 + tig + ((q >> 1) & 1) * 4;   // word index in [0,320)
        int k  = (2 * bw) >> 7;
        int ci = (2 * bw) & 127;
        float v0 = conv_w[(co * 128 + ci) * 5 + k];
        float v1 = conv_w[(co * 128 + ci + 1) * 5 + k];
        unsigned uh, ul; split2(v0, v1, uh, ul);
        g_wpk_hi[idx] = uh; g_wpk_lo[idx] = ul;
    }
    if (idx < 2 * 8 * 8 * 64) {
        int r    = idx & 1;
        int lane = (idx >> 1) & 31;
        int ni   = (idx >> 6) & 7;
        int kk   = (idx >> 9) & 7;
        int wn   = idx >> 12;
        int gid = lane >> 2, tig = lane & 3;
        int gg = wn * 64 + ni * 8 + gid;
        int j  = kk * 8 + tig + r * 4;               // word index in [0,64)
        float v0 = Wih1[gg * 128 + 2 * j];
        float v1 = Wih1[gg * 128 + 2 * j + 1];
        unsigned uh, ul; split2(v0, v1, uh, ul);
        g_w1k_hi[idx] = uh; g_w1k_lo[idx] = ul;
    }
}

// ---------------- Kernel 1: conv1d via bf16-split tensor-core GEMM ----------------
#define LOADA(s, AH, AL) do {                                                  \
    const uint4* ph_ = (const uint4*)&g_wpk_hi[((wm * 40 + (s)) * 32 + lane) * 8]; \
    *(uint4*)&AH[0][0] = ph_[0];                                               \
    *(uint4*)&AH[1][0] = ph_[1];                                               \
    const uint4* pl_ = (const uint4*)&g_wpk_lo[((wm * 40 + (s)) * 32 + lane) * 8]; \
    *(uint4*)&AL[0][0] = pl_[0];                                               \
    *(uint4*)&AL[1][0] = pl_[1];                                               \
} while (0)

#define MMASTEP(s, AH, AL) do {                                                \
    int k5_ = (s) >> 3; int crow_ = ((s) & 7) * 8;                             \
    _Pragma("unroll")                                                          \
    for (int ni = 0; ni < 8; ++ni) {                                           \
        int r_ = (wn * 64 + ni * 8 + gid + k5_) * 68 + crow_ + tig;            \
        unsigned bh0 = sH[r_], bh1 = sH[r_ + 4];                               \
        unsigned bl0 = sL[r_], bl1 = sL[r_ + 4];                               \
        _Pragma("unroll")                                                      \
        for (int mi = 0; mi < 2; ++mi) {                                       \
            MMA_BF16(acc[mi][ni], AH[mi][0],AH[mi][1],AH[mi][2],AH[mi][3], bh0,bh1); \
            MMA_BF16(acc[mi][ni], AH[mi][0],AH[mi][1],AH[mi][2],AH[mi][3], bl0,bl1); \
            MMA_BF16(acc[mi][ni], AL[mi][0],AL[mi][1],AL[mi][2],AL[mi][3], bh0,bh1); \
        }                                                                      \
    }                                                                          \
} while (0)

__global__ void __launch_bounds__(256) conv_mma_kernel(const float* __restrict__ x,
                                                       const float* __restrict__ cb) {
    extern __shared__ unsigned sm[];
    unsigned* sH = sm;               // 136 rows * 68 words
    unsigned* sL = sm + 136 * 68;

    int tid  = threadIdx.x;
    int warp = tid >> 5, lane = tid & 31;
    int gid  = lane >> 2, tig = lane & 3;
    int wm   = warp & 3;
    int wn   = warp >> 2;
    int l0   = blockIdx.x * 128;
    int b    = blockIdx.y;

    const float* xb = x + (size_t)b * XBSTR;
    for (int it = warp; it < 17 * 16; it += 8) {
        int jb  = (it >> 4) * 8;
        int cwb = (it & 15) * 4;
        int j  = jb + (lane >> 2);
        int cw = cwb + (lane & 3);
        int l  = l0 + j;
        int ci = cw * 2;
        float v0 = 0.0f, v1 = 0.0f;
        if (l < LIN) { v0 = xb[ci * LIN + l]; v1 = xb[(ci + 1) * LIN + l]; }
        unsigned uh, ul; split2(v0, v1, uh, ul);
        sH[j * 68 + cw] = uh;
        sL[j * 68 + cw] = ul;
    }
    __syncthreads();

    float acc[2][8][4];
    #pragma unroll
    for (int mi = 0; mi < 2; ++mi)
        #pragma unroll
        for (int ni = 0; ni < 8; ++ni)
            #pragma unroll
            for (int q = 0; q < 4; ++q) acc[mi][ni][q] = 0.0f;

    unsigned A0h[2][4], A0l[2][4], A1h[2][4], A1l[2][4];
    LOADA(0, A0h, A0l);
    for (int s = 0; s < 40; s += 2) {
        LOADA(s + 1, A1h, A1l);
        MMASTEP(s, A0h, A0l);
        if (s + 2 < 40) LOADA(s + 2, A0h, A0l);
        MMASTEP(s + 1, A1h, A1l);
    }

    int co_base0 = wm * 32 + gid;
    __nv_bfloat16* oh = g_seq_hi + (size_t)b * CBSTR;
    __nv_bfloat16* ol = g_seq_lo + (size_t)b * CBSTR;
    #pragma unroll
    for (int mi = 0; mi < 2; ++mi) {
        int coA = co_base0 + mi * 16;
        int coB = coA + 8;
        float biasA = cb[coA], biasB = cb[coB];
        #pragma unroll
        for (int ni = 0; ni < 8; ++ni) {
            int lg = l0 + wn * 64 + ni * 8 + tig * 2;
            if (lg < LOUT) {
                unsigned uh, ul;
                int fA = coA * LOUT + lg;
                split2(acc[mi][ni][0] + biasA, acc[mi][ni][1] + biasA, uh, ul);
                *(unsigned*)(oh + fA) = uh; *(unsigned*)(ol + fA) = ul;
                int fB = coB * LOUT + lg;
                split2(acc[mi][ni][2] + biasB, acc[mi][ni][3] + biasB, uh, ul);
                *(unsigned*)(oh + fB) = uh; *(unsigned*)(ol + fB) = ul;
            }
        }
    }
}

// ---------------- Kernel 2: xg = seq @ Wih1^T + bias via bf16-split mma ----------------
__global__ void __launch_bounds__(256) xg_mma_kernel(const float* __restrict__ bih1,
                                                     const float* __restrict__ bhh1) {
    extern __shared__ unsigned sm[];
    unsigned* sH = sm;               // 128 rows * 68 words
    unsigned* sL = sm + 128 * 68;

    int tid  = threadIdx.x;
    int warp = tid >> 5, lane = tid & 31;
    int gid  = lane >> 2, tig = lane & 3;
    int wm   = warp & 3;
    int wn   = warp >> 2;
    int t0   = blockIdx.x * 128;
    int b    = blockIdx.y;

    const __nv_bfloat16* shd = g_seq_hi + (size_t)b * CBSTR;
    const __nv_bfloat16* sld = g_seq_lo + (size_t)b * CBSTR;
    for (int row = warp; row < 128; row += 8) {
        int t = t0 + row;
        int d = lane * 4;
        uint2 vh = make_uint2(0u, 0u), vl = make_uint2(0u, 0u);
        if (t < TT) {
            vh = *(const uint2*)(shd + (size_t)t * D1 + d);
            vl = *(const uint2*)(sld + (size_t)t * D1 + d);
        }
        *(uint2*)((__nv_bfloat16*)sH + row * 136 + d) = vh;
        *(uint2*)((__nv_bfloat16*)sL + row * 136 + d) = vl;
    }
    __syncthreads();

    float acc[2][8][4];
    #pragma unroll
    for (int mi = 0; mi < 2; ++mi)
        #pragma unroll
        for (int ni = 0; ni < 8; ++ni)
            #pragma unroll
            for (int q = 0; q < 4; ++q) acc[mi][ni][q] = 0.0f;

    #pragma unroll
    for (int kk = 0; kk < 8; ++kk) {
        unsigned ah[2][4], al[2][4];
        #pragma unroll
        for (int mi = 0; mi < 2; ++mi) {
            int r = (wm * 32 + mi * 16 + gid) * 68 + kk * 8 + tig;
            ah[mi][0] = sH[r];           ah[mi][1] = sH[r + 8 * 68];
            ah[mi][2] = sH[r + 4];       ah[mi][3] = sH[r + 8 * 68 + 4];
            al[mi][0] = sL[r];           al[mi][1] = sL[r + 8 * 68];
            al[mi][2] = sL[r + 4];       al[mi][3] = sL[r + 8 * 68 + 4];
        }
        #pragma unroll
        for (int ni = 0; ni < 8; ++ni) {
            int wi = ((wn * 8 + kk) * 8 + ni) * 64 + lane * 2;
            uint2 wh = *(const uint2*)&g_w1k_hi[wi];
            uint2 wl = *(const uint2*)&g_w1k_lo[wi];
            #pragma unroll
            for (int mi = 0; mi < 2; ++mi) {
                MMA_BF16(acc[mi][ni], ah[mi][0], ah[mi][1], ah[mi][2], ah[mi][3], wh.x, wh.y);
                MMA_BF16(acc[mi][ni], ah[mi][0], ah[mi][1], ah[mi][2], ah[mi][3], wl.x, wl.y);
                MMA_BF16(acc[mi][ni], al[mi][0], al[mi][1], al[mi][2], al[mi][3], wh.x, wh.y);
            }
        }
    }

    float* xgb = g_xg + (size_t)b * CBSTR;
    #pragma unroll
    for (int ni = 0; ni < 8; ++ni) {
        int gcol = wn * 64 + ni * 8 + tig * 2;
        float bi0 = bih1[gcol] + bhh1[gcol];
        float bi1 = bih1[gcol + 1] + bhh1[gcol + 1];
        #pragma unroll
        for (int mi = 0; mi < 2; ++mi) {
            int tA = t0 + wm * 32 + mi * 16 + gid;
            if (tA < TT) {
                float2 v = make_float2(acc[mi][ni][0] + bi0, acc[mi][ni][1] + bi1);
                *(float2*)(xgb + (size_t)tA * D1 + gcol) = v;
            }
            int tB = tA + 8;
            if (tB < TT) {
                float2 v = make_float2(acc[mi][ni][2] + bi0, acc[mi][ni][3] + bi1);
                *(float2*)(xgb + (size_t)tB * D1 + gcol) = v;
            }
        }
    }
}

// ---------------- Kernel 3: pipelined 3-layer LSTM, 4 batches per CTA ----------------
// Tick τ: L1 computes t=τ, L2 t=τ-1, L3 t=τ-2, concurrently; one barrier/tick.
// 4 batches per CTA: weights register-resident once; 4-way independent FMA
// chains per thread hide latency. grid = B/4 = 128 <= 148 SMs (even load).
__global__ void __launch_bounds__(160, 2) lstm_kernel(
    const float* __restrict__ Whh1,
    const float* __restrict__ Wih2, const float* __restrict__ Whh2,
    const float* __restrict__ bih2, const float* __restrict__ bhh2,
    const float* __restrict__ Wih3, const float* __restrict__ Whh3,
    const float* __restrict__ bih3, const float* __restrict__ bhh3,
    float* __restrict__ out)
{
    __shared__ float h1s[2][4][32], h2s[2][4][16], h3s[2][4][32]; // [phase][batch][cell]

    int tid = threadIdx.x;
    int bb = blockIdx.x * 4;
    bool isL1 = tid < 64;
    bool isL2 = (tid >= 64) & (tid < 96);
    int local = isL1 ? tid : (isL2 ? tid - 64 : tid - 96);
    int cell = local >> 1;
    int half = local & 1;              // 0: (i,g)   1: (f,o)
    int H = isL2 ? 16 : 32;
    int ga = half ? H + cell : cell;
    int gb = half ? 3 * H + cell : 2 * H + cell;

    float4 wLa[8], wLb[8], wSa[4], wSb[4];
    float biasa = 0.f, biasb = 0.f;
    if (isL1) {
        #pragma unroll
        for (int i = 0; i < 8; ++i) {
            wLa[i] = *(const float4*)(Whh1 + ga * 32 + i * 4);
            wLb[i] = *(const float4*)(Whh1 + gb * 32 + i * 4);
        }
    } else if (isL2) {
        #pragma unroll
        for (int i = 0; i < 8; ++i) {
            wLa[i] = *(const float4*)(Wih2 + ga * 32 + i * 4);
            wLb[i] = *(const float4*)(Wih2 + gb * 32 + i * 4);
        }
        #pragma unroll
        for (int i = 0; i < 4; ++i) {
            wSa[i] = *(const float4*)(Whh2 + ga * 16 + i * 4);
            wSb[i] = *(const float4*)(Whh2 + gb * 16 + i * 4);
        }
        biasa = bih2[ga] + bhh2[ga];
        biasb = bih2[gb] + bhh2[gb];
    } else {
        #pragma unroll
        for (int i = 0; i < 8; ++i) {
            wLa[i] = *(const float4*)(Whh3 + ga * 32 + i * 4);
            wLb[i] = *(const float4*)(Whh3 + gb * 32 + i * 4);
        }
        #pragma unroll
        for (int i = 0; i < 4; ++i) {
            wSa[i] = *(const float4*)(Wih3 + ga * 16 + i * 4);
            wSb[i] = *(const float4*)(Wih3 + gb * 16 + i * 4);
        }
        biasa = bih3[ga] + bhh3[ga];
        biasb = bih3[gb] + bhh3[gb];
    }

    for (int i = tid; i < 2 * 4 * 32; i += 160) ((float*)h1s)[i] = 0.f;
    for (int i = tid; i < 2 * 4 * 16; i += 160) ((float*)h2s)[i] = 0.f;
    for (int i = tid; i < 2 * 4 * 32; i += 160) ((float*)h3s)[i] = 0.f;
    float cst[4] = {0.f, 0.f, 0.f, 0.f};
    __syncthreads();

    const float* xgp0 = g_xg + (size_t)bb * CBSTR;
    const float* xgp1 = xgp0 + CBSTR;
    const float* xgp2 = xgp1 + CBSTR;
    const float* xgp3 = xgp2 + CBSTR;
    float xa[4] = {0,0,0,0}, xb[4] = {0,0,0,0};
    if (isL1) {
        xa[0] = xgp0[ga]; xb[0] = xgp0[gb];
        xa[1] = xgp1[ga]; xb[1] = xgp1[gb];
        xa[2] = xgp2[ga]; xb[2] = xgp2[gb];
        xa[3] = xgp3[ga]; xb[3] = xgp3[gb];
    }

    #define COMBINE4(PA, PB, DST) do {                                         \
        _Pragma("unroll")                                                      \
        for (int u = 0; u < 4; ++u) {                                          \
            float va_ = sigf(PA[u]);                                           \
            float vb_ = half ? sigf(PB[u]) : tanhfast(PB[u]);                  \
            float pay_ = va_ * vb_;                                            \
            float got_ = __shfl_xor_sync(0xffffffffu, pay_, 1);                \
            if (half) {                                                        \
                cst[u] = fmaf(va_, cst[u], got_);                              \
                (DST)[u][cell] = vb_ * tanhfast(cst[u]);                       \
            }                                                                  \
        }                                                                      \
    } while (0)

    #define GEMV4_L(BUF, A0, A1, B0, B1) do {                                  \
        _Pragma("unroll")                                                      \
        for (int i = 0; i < 8; ++i) {                                          \
            float4 wa_ = wLa[i], wb_ = wLb[i];                                 \
            _Pragma("unroll")                                                  \
            for (int u = 0; u < 4; ++u) {                                      \
                float4 h = ((const float4*)(BUF)[u])[i];                       \
                A0[u] = fmaf(h.x, wa_.x, A0[u]); A1[u] = fmaf(h.y, wa_.y, A1[u]); \
                A0[u] = fmaf(h.z, wa_.z, A0[u]); A1[u] = fmaf(h.w, wa_.w, A1[u]); \
                B0[u] = fmaf(h.x, wb_.x, B0[u]); B1[u] = fmaf(h.y, wb_.y, B1[u]); \
                B0[u] = fmaf(h.z, wb_.z, B0[u]); B1[u] = fmaf(h.w, wb_.w, B1[u]); \
            }                                                                  \
        }                                                                      \
    } while (0)

    #define GEMV4_S(BUF, A0, A1, B0, B1) do {                                  \
        _Pragma("unroll")                                                      \
        for (int i = 0; i < 4; ++i) {                                          \
            float4 wa_ = wSa[i], wb_ = wSb[i];                                 \
            _Pragma("unroll")                                                  \
            for (int u = 0; u < 4; ++u) {                                      \
                float4 h = ((const float4*)(BUF)[u])[i];                       \
                A0[u] = fmaf(h.x, wa_.x, A0[u]); A1[u] = fmaf(h.y, wa_.y, A1[u]); \
                A0[u] = fmaf(h.z, wa_.z, A0[u]); A1[u] = fmaf(h.w, wa_.w, A1[u]); \
                B0[u] = fmaf(h.x, wb_.x, B0[u]); B1[u] = fmaf(h.y, wb_.y, B1[u]); \
                B0[u] = fmaf(h.z, wb_.z, B0[u]); B1[u] = fmaf(h.w, wb_.w, B1[u]); \
            }                                                                  \
        }                                                                      \
    } while (0)

    for (int tau = 0; tau < TT + 2; ++tau) {
        int wp = tau & 1, rp = wp ^ 1;

        if (isL1) {
            if (tau < TT) {
                float A0[4], A1[4], B0[4], B1[4];
                #pragma unroll
                for (int u = 0; u < 4; ++u) {
                    A0[u] = xa[u]; A1[u] = 0.f; B0[u] = xb[u]; B1[u] = 0.f;
                }
                GEMV4_L(h1s[rp], A0, A1, B0, B1);
                if (tau + 1 < TT) {
                    size_t off = (size_t)(tau + 1) * D1;
                    xa[0] = xgp0[off + ga]; xb[0] = xgp0[off + gb];
                    xa[1] = xgp1[off + ga]; xb[1] = xgp1[off + gb];
                    xa[2] = xgp2[off + ga]; xb[2] = xgp2[off + gb];
                    xa[3] = xgp3[off + ga]; xb[3] = xgp3[off + gb];
                }
                float PA[4], PB[4];
                #pragma unroll
                for (int u = 0; u < 4; ++u) { PA[u] = A0[u] + A1[u]; PB[u] = B0[u] + B1[u]; }
                COMBINE4(PA, PB, h1s[wp]);
            }
        } else if (isL2) {
            if (tau >= 1 && tau <= TT) {
                float A0[4], A1[4], B0[4], B1[4];
                #pragma unroll
                for (int u = 0; u < 4; ++u) {
                    A0[u] = biasa; A1[u] = 0.f; B0[u] = biasb; B1[u] = 0.f;
                }
                GEMV4_L(h1s[rp], A0, A1, B0, B1);
                GEMV4_S(h2s[rp], A0, A1, B0, B1);
                float PA[4], PB[4];
                #pragma unroll
                for (int u = 0; u < 4; ++u) { PA[u] = A0[u] + A1[u]; PB[u] = B0[u] + B1[u]; }
                COMBINE4(PA, PB, h2s[wp]);
            }
        } else {
            if (tau >= 2) {
                float A0[4], A1[4], B0[4], B1[4];
                #pragma unroll
                for (int u = 0; u < 4; ++u) {
                    A0[u] = biasa; A1[u] = 0.f; B0[u] = biasb; B1[u] = 0.f;
                }
                GEMV4_S(h2s[rp], A0, A1, B0, B1);
                GEMV4_L(h3s[rp], A0, A1, B0, B1);
                float PA[4], PB[4];
                #pragma unroll
                for (int u = 0; u < 4; ++u) { PA[u] = A0[u] + A1[u]; PB[u] = B0[u] + B1[u]; }
                COMBINE4(PA, PB, h3s[wp]);
            }
        }
        __syncthreads();
    }

    if (tid < 32) {
        int fp = (TT + 1) & 1;
        #pragma unroll
        for (int u = 0; u < 4; ++u)
            out[(bb + u) * 32 + tid] = h3s[fp][u][tid];
    }
}

// ---------------- launch ----------------
extern "C" void kernel_launch(void* const* d_in, const int* in_sizes, int n_in,
                              void* d_out, int out_size) {
    const float* x      = (const float*)d_in[0];
    const float* conv_w = (const float*)d_in[1];
    const float* conv_b = (const float*)d_in[2];
    const float* Wih1   = (const float*)d_in[3];
    const float* Whh1   = (const float*)d_in[4];
    const float* bih1   = (const float*)d_in[5];
    const float* bhh1   = (const float*)d_in[6];
    const float* Wih2   = (const float*)d_in[7];
    const float* Whh2   = (const float*)d_in[8];
    const float* bih2   = (const float*)d_in[9];
    const float* bhh2   = (const float*)d_in[10];
    const float* Wih3   = (const float*)d_in[11];
    const float* Whh3   = (const float*)d_in[12];
    const float* bih3   = (const float*)d_in[13];
    const float* bhh3   = (const float*)d_in[14];
    float* out = (float*)d_out;

    const int conv_smem = 2 * 136 * 68 * 4;   // 73984 B
    const int xg_smem   = 2 * 128 * 68 * 4;   // 69632 B
    cudaFuncSetAttribute(conv_mma_kernel, cudaFuncAttributeMaxDynamicSharedMemorySize, conv_smem);
    cudaFuncSetAttribute(xg_mma_kernel,   cudaFuncAttributeMaxDynamicSharedMemorySize, xg_smem);

    prep_kernel<<<160, 256>>>(conv_w, Wih1);
    conv_mma_kernel<<<dim3(8, B), 256, conv_smem>>>(x, conv_b);
    xg_mma_kernel<<<dim3(8, B), 256, xg_smem>>>(bih1, bhh1);
    lstm_kernel<<<B / 4, 160>>>(Whh1, Wih2, Whh2, bih2, bhh2,
                                Wih3, Whh3, bih3, bhh3, out);
}

// round 15
// speedup vs baseline: 1.3058x; 1.3058x over previous
#include <cuda_runtime.h>
#include <cuda_bf16.h>
#include <cstdint>

// Problem dims
#define B     512
#define CIN   128
#define LIN   1024
#define KW    5
#define LOUT  1020
#define TT    1020
#define D1    128

#define XBSTR   (CIN*LIN)        // 131072
#define CBSTR   (CIN*LOUT)       // 130560 == TT*D1

// ---- scratch (device globals; no runtime allocation allowed) ----
__device__ __nv_bfloat16 g_seq_hi[(size_t)B * CBSTR];
__device__ __nv_bfloat16 g_seq_lo[(size_t)B * CBSTR];
__device__ float         g_xg   [(size_t)B * CBSTR];
// load-linear repacked fragments
__device__ unsigned      g_wpk_hi[4 * 40 * 32 * 8];   // [wm][slice][lane][8]
__device__ unsigned      g_wpk_lo[4 * 40 * 32 * 8];
__device__ unsigned      g_w1k_hi[2 * 8 * 8 * 64];    // [wn][kk][ni][lane*2+r]
__device__ unsigned      g_w1k_lo[2 * 8 * 8 * 64];

__device__ __forceinline__ float sigf(float x) {
    return __fdividef(1.0f, 1.0f + __expf(-x));
}
__device__ __forceinline__ float tanhfast(float x) {
    x = fminf(15.0f, fmaxf(-15.0f, x));
    float e = __expf(2.0f * x);
    return __fdividef(e - 1.0f, e + 1.0f);
}

__device__ __forceinline__ void split2(float v0, float v1, unsigned &uh, unsigned &ul) {
    __nv_bfloat16 h0 = __float2bfloat16_rn(v0);
    __nv_bfloat16 h1 = __float2bfloat16_rn(v1);
    float r0 = v0 - __bfloat162float(h0);
    float r1 = v1 - __bfloat162float(h1);
    __nv_bfloat162 ph; ph.x = h0; ph.y = h1;
    __nv_bfloat162 pl; pl.x = __float2bfloat16_rn(r0); pl.y = __float2bfloat16_rn(r1);
    uh = *(unsigned*)&ph;
    ul = *(unsigned*)&pl;
}

#define MMA_BF16(d, a0,a1,a2,a3, b0,b1)                                     \
    asm volatile("mma.sync.aligned.m16n8k16.row.col.f32.bf16.bf16.f32 "     \
        "{%0,%1,%2,%3},{%4,%5,%6,%7},{%8,%9},{%0,%1,%2,%3};"                \
        : "+f"(d[0]), "+f"(d[1]), "+f"(d[2]), "+f"(d[3])                    \
        : "r"(a0), "r"(a1), "r"(a2), "r"(a3), "r"(b0), "r"(b1))

// ---------------- Kernel 0: pack weights DIRECTLY into load-linear order ----------------
__global__ void prep_kernel(const float* __restrict__ conv_w, const float* __restrict__ Wih1) {
    int idx = blockIdx.x * 256 + threadIdx.x;
    if (idx < 4 * 40 * 32 * 8) {
        int q    = idx & 7;
        int lane = (idx >> 3) & 31;
        int s    = (idx >> 8) % 40;
        int wm   = idx / (40 * 256);
        int gid = lane >> 2, tig = lane & 3;
        int co = wm * 32 + gid + ((q >> 2) & 1) * 16 + (q & 1) * 8;
        int bw = s * 8 + tig + ((q >> 1) & 1) * 4;   // word index in [0,320)
        int k  = (2 * bw) >> 7;
        int ci = (2 * bw) & 127;
        float v0 = conv_w[(co * 128 + ci) * 5 + k];
        float v1 = conv_w[(co * 128 + ci + 1) * 5 + k];
        unsigned uh, ul; split2(v0, v1, uh, ul);
        g_wpk_hi[idx] = uh; g_wpk_lo[idx] = ul;
    }
    if (idx < 2 * 8 * 8 * 64) {
        int r    = idx & 1;
        int lane = (idx >> 1) & 31;
        int ni   = (idx >> 6) & 7;
        int kk   = (idx >> 9) & 7;
        int wn   = idx >> 12;
        int gid = lane >> 2, tig = lane & 3;
        int gg = wn * 64 + ni * 8 + gid;
        int j  = kk * 8 + tig + r * 4;               // word index in [0,64)
        float v0 = Wih1[gg * 128 + 2 * j];
        float v1 = Wih1[gg * 128 + 2 * j + 1];
        unsigned uh, ul; split2(v0, v1, uh, ul);
        g_w1k_hi[idx] = uh; g_w1k_lo[idx] = ul;
    }
}

// ---------------- Kernel 1: conv1d via bf16-split tensor-core GEMM ----------------
#define LOADA(s, AH, AL) do {                                                  \
    const uint4* ph_ = (const uint4*)&g_wpk_hi[((wm * 40 + (s)) * 32 + lane) * 8]; \
    *(uint4*)&AH[0][0] = ph_[0];                                               \
    *(uint4*)&AH[1][0] = ph_[1];                                               \
    const uint4* pl_ = (const uint4*)&g_wpk_lo[((wm * 40 + (s)) * 32 + lane) * 8]; \
    *(uint4*)&AL[0][0] = pl_[0];                                               \
    *(uint4*)&AL[1][0] = pl_[1];                                               \
} while (0)

#define MMASTEP(s, AH, AL) do {                                                \
    int k5_ = (s) >> 3; int crow_ = ((s) & 7) * 8;                             \
    _Pragma("unroll")                                                          \
    for (int ni = 0; ni < 8; ++ni) {                                           \
        int r_ = (wn * 64 + ni * 8 + gid + k5_) * 68 + crow_ + tig;            \
        unsigned bh0 = sH[r_], bh1 = sH[r_ + 4];                               \
        unsigned bl0 = sL[r_], bl1 = sL[r_ + 4];                               \
        _Pragma("unroll")                                                      \
        for (int mi = 0; mi < 2; ++mi) {                                       \
            MMA_BF16(acc[mi][ni], AH[mi][0],AH[mi][1],AH[mi][2],AH[mi][3], bh0,bh1); \
            MMA_BF16(acc[mi][ni], AH[mi][0],AH[mi][1],AH[mi][2],AH[mi][3], bl0,bl1); \
            MMA_BF16(acc[mi][ni], AL[mi][0],AL[mi][1],AL[mi][2],AL[mi][3], bh0,bh1); \
        }                                                                      \
    }                                                                          \
} while (0)

__global__ void __launch_bounds__(256) conv_mma_kernel(const float* __restrict__ x,
                                                       const float* __restrict__ cb) {
    extern __shared__ unsigned sm[];
    unsigned* sH = sm;               // 136 rows * 68 words
    unsigned* sL = sm + 136 * 68;

    int tid  = threadIdx.x;
    int warp = tid >> 5, lane = tid & 31;
    int gid  = lane >> 2, tig = lane & 3;
    int wm   = warp & 3;
    int wn   = warp >> 2;
    int l0   = blockIdx.x * 128;
    int b    = blockIdx.y;

    const float* xb = x + (size_t)b * XBSTR;
    for (int it = warp; it < 17 * 16; it += 8) {
        int jb  = (it >> 4) * 8;
        int cwb = (it & 15) * 4;
        int j  = jb + (lane >> 2);
        int cw = cwb + (lane & 3);
        int l  = l0 + j;
        int ci = cw * 2;
        float v0 = 0.0f, v1 = 0.0f;
        if (l < LIN) { v0 = xb[ci * LIN + l]; v1 = xb[(ci + 1) * LIN + l]; }
        unsigned uh, ul; split2(v0, v1, uh, ul);
        sH[j * 68 + cw] = uh;
        sL[j * 68 + cw] = ul;
    }
    __syncthreads();

    float acc[2][8][4];
    #pragma unroll
    for (int mi = 0; mi < 2; ++mi)
        #pragma unroll
        for (int ni = 0; ni < 8; ++ni)
            #pragma unroll
            for (int q = 0; q < 4; ++q) acc[mi][ni][q] = 0.0f;

    unsigned A0h[2][4], A0l[2][4], A1h[2][4], A1l[2][4];
    LOADA(0, A0h, A0l);
    for (int s = 0; s < 40; s += 2) {
        LOADA(s + 1, A1h, A1l);
        MMASTEP(s, A0h, A0l);
        if (s + 2 < 40) LOADA(s + 2, A0h, A0l);
        MMASTEP(s + 1, A1h, A1l);
    }

    int co_base0 = wm * 32 + gid;
    __nv_bfloat16* oh = g_seq_hi + (size_t)b * CBSTR;
    __nv_bfloat16* ol = g_seq_lo + (size_t)b * CBSTR;
    #pragma unroll
    for (int mi = 0; mi < 2; ++mi) {
        int coA = co_base0 + mi * 16;
        int coB = coA + 8;
        float biasA = cb[coA], biasB = cb[coB];
        #pragma unroll
        for (int ni = 0; ni < 8; ++ni) {
            int lg = l0 + wn * 64 + ni * 8 + tig * 2;
            if (lg < LOUT) {
                unsigned uh, ul;
                int fA = coA * LOUT + lg;
                split2(acc[mi][ni][0] + biasA, acc[mi][ni][1] + biasA, uh, ul);
                *(unsigned*)(oh + fA) = uh; *(unsigned*)(ol + fA) = ul;
                int fB = coB * LOUT + lg;
                split2(acc[mi][ni][2] + biasB, acc[mi][ni][3] + biasB, uh, ul);
                *(unsigned*)(oh + fB) = uh; *(unsigned*)(ol + fB) = ul;
            }
        }
    }
}

// ---------------- Kernel 2: xg = seq @ Wih1^T + bias via bf16-split mma ----------------
// __launch_bounds__(256, 3): cap regs at ~84 so 3 CTAs co-reside per SM
// (smem 69632*3 = 209KB fits). Latency-bound kernel -> occupancy beats spills.
__global__ void __launch_bounds__(256, 3) xg_mma_kernel(const float* __restrict__ bih1,
                                                        const float* __restrict__ bhh1) {
    extern __shared__ unsigned sm[];
    unsigned* sH = sm;               // 128 rows * 68 words
    unsigned* sL = sm + 128 * 68;

    int tid  = threadIdx.x;
    int warp = tid >> 5, lane = tid & 31;
    int gid  = lane >> 2, tig = lane & 3;
    int wm   = warp & 3;
    int wn   = warp >> 2;
    int t0   = blockIdx.x * 128;
    int b    = blockIdx.y;

    const __nv_bfloat16* shd = g_seq_hi + (size_t)b * CBSTR;
    const __nv_bfloat16* sld = g_seq_lo + (size_t)b * CBSTR;
    for (int row = warp; row < 128; row += 8) {
        int t = t0 + row;
        int d = lane * 4;
        uint2 vh = make_uint2(0u, 0u), vl = make_uint2(0u, 0u);
        if (t < TT) {
            vh = *(const uint2*)(shd + (size_t)t * D1 + d);
            vl = *(const uint2*)(sld + (size_t)t * D1 + d);
        }
        *(uint2*)((__nv_bfloat16*)sH + row * 136 + d) = vh;
        *(uint2*)((__nv_bfloat16*)sL + row * 136 + d) = vl;
    }
    __syncthreads();

    float acc[2][8][4];
    #pragma unroll
    for (int mi = 0; mi < 2; ++mi)
        #pragma unroll
        for (int ni = 0; ni < 8; ++ni)
            #pragma unroll
            for (int q = 0; q < 4; ++q) acc[mi][ni][q] = 0.0f;

    #pragma unroll
    for (int kk = 0; kk < 8; ++kk) {
        unsigned ah[2][4], al[2][4];
        #pragma unroll
        for (int mi = 0; mi < 2; ++mi) {
            int r = (wm * 32 + mi * 16 + gid) * 68 + kk * 8 + tig;
            ah[mi][0] = sH[r];           ah[mi][1] = sH[r + 8 * 68];
            ah[mi][2] = sH[r + 4];       ah[mi][3] = sH[r + 8 * 68 + 4];
            al[mi][0] = sL[r];           al[mi][1] = sL[r + 8 * 68];
            al[mi][2] = sL[r + 4];       al[mi][3] = sL[r + 8 * 68 + 4];
        }
        #pragma unroll
        for (int ni = 0; ni < 8; ++ni) {
            int wi = ((wn * 8 + kk) * 8 + ni) * 64 + lane * 2;
            uint2 wh = *(const uint2*)&g_w1k_hi[wi];
            uint2 wl = *(const uint2*)&g_w1k_lo[wi];
            #pragma unroll
            for (int mi = 0; mi < 2; ++mi) {
                MMA_BF16(acc[mi][ni], ah[mi][0], ah[mi][1], ah[mi][2], ah[mi][3], wh.x, wh.y);
                MMA_BF16(acc[mi][ni], ah[mi][0], ah[mi][1], ah[mi][2], ah[mi][3], wl.x, wl.y);
                MMA_BF16(acc[mi][ni], al[mi][0], al[mi][1], al[mi][2], al[mi][3], wh.x, wh.y);
            }
        }
    }

    float* xgb = g_xg + (size_t)b * CBSTR;
    #pragma unroll
    for (int ni = 0; ni < 8; ++ni) {
        int gcol = wn * 64 + ni * 8 + tig * 2;
        float bi0 = bih1[gcol] + bhh1[gcol];
        float bi1 = bih1[gcol + 1] + bhh1[gcol + 1];
        #pragma unroll
        for (int mi = 0; mi < 2; ++mi) {
            int tA = t0 + wm * 32 + mi * 16 + gid;
            if (tA < TT) {
                float2 v = make_float2(acc[mi][ni][0] + bi0, acc[mi][ni][1] + bi1);
                *(float2*)(xgb + (size_t)tA * D1 + gcol) = v;
            }
            int tB = tA + 8;
            if (tB < TT) {
                float2 v = make_float2(acc[mi][ni][2] + bi0, acc[mi][ni][3] + bi1);
                *(float2*)(xgb + (size_t)tB * D1 + gcol) = v;
            }
        }
    }
}

// ---------------- Kernel 3: pipelined 3-layer LSTM, 2 batches per CTA ----------------
// (Exact R11 configuration: grid 256 -> ~2 CTAs/SM, cross-CTA barrier overlap.)
__global__ void __launch_bounds__(160, 2) lstm_kernel(
    const float* __restrict__ Whh1,
    const float* __restrict__ Wih2, const float* __restrict__ Whh2,
    const float* __restrict__ bih2, const float* __restrict__ bhh2,
    const float* __restrict__ Wih3, const float* __restrict__ Whh3,
    const float* __restrict__ bih3, const float* __restrict__ bhh3,
    float* __restrict__ out)
{
    __shared__ float h1s[2][2][32], h2s[2][2][16], h3s[2][2][32]; // [batch][phase][cell]

    int tid = threadIdx.x;
    int bb = blockIdx.x * 2;
    bool isL1 = tid < 64;
    bool isL2 = (tid >= 64) & (tid < 96);
    int local = isL1 ? tid : (isL2 ? tid - 64 : tid - 96);
    int cell = local >> 1;
    int half = local & 1;              // 0: (i,g)   1: (f,o)
    int H = isL2 ? 16 : 32;
    int ga = half ? H + cell : cell;
    int gb = half ? 3 * H + cell : 2 * H + cell;

    float4 wLa[8], wLb[8], wSa[4], wSb[4];
    float biasa = 0.f, biasb = 0.f;
    if (isL1) {
        #pragma unroll
        for (int i = 0; i < 8; ++i) {
            wLa[i] = *(const float4*)(Whh1 + ga * 32 + i * 4);
            wLb[i] = *(const float4*)(Whh1 + gb * 32 + i * 4);
        }
    } else if (isL2) {
        #pragma unroll
        for (int i = 0; i < 8; ++i) {
            wLa[i] = *(const float4*)(Wih2 + ga * 32 + i * 4);
            wLb[i] = *(const float4*)(Wih2 + gb * 32 + i * 4);
        }
        #pragma unroll
        for (int i = 0; i < 4; ++i) {
            wSa[i] = *(const float4*)(Whh2 + ga * 16 + i * 4);
            wSb[i] = *(const float4*)(Whh2 + gb * 16 + i * 4);
        }
        biasa = bih2[ga] + bhh2[ga];
        biasb = bih2[gb] + bhh2[gb];
    } else {
        #pragma unroll
        for (int i = 0; i < 8; ++i) {
            wLa[i] = *(const float4*)(Whh3 + ga * 32 + i * 4);
            wLb[i] = *(const float4*)(Whh3 + gb * 32 + i * 4);
        }
        #pragma unroll
        for (int i = 0; i < 4; ++i) {
            wSa[i] = *(const float4*)(Wih3 + ga * 16 + i * 4);
            wSb[i] = *(const float4*)(Wih3 + gb * 16 + i * 4);
        }
        biasa = bih3[ga] + bhh3[ga];
        biasb = bih3[gb] + bhh3[gb];
    }

    if (tid < 32) {
        h1s[0][0][tid] = 0.f; h1s[0][1][tid] = 0.f;
        h1s[1][0][tid] = 0.f; h1s[1][1][tid] = 0.f;
        h3s[0][0][tid] = 0.f; h3s[0][1][tid] = 0.f;
        h3s[1][0][tid] = 0.f; h3s[1][1][tid] = 0.f;
    }
    if (tid < 16) {
        h2s[0][0][tid] = 0.f; h2s[0][1][tid] = 0.f;
        h2s[1][0][tid] = 0.f; h2s[1][1][tid] = 0.f;
    }
    float cst0 = 0.f, cst1 = 0.f;
    __syncthreads();

    const float* xg0 = g_xg + (size_t)bb * CBSTR;
    const float* xg1 = g_xg + (size_t)(bb + 1) * CBSTR;
    float xa0 = 0.f, xb0 = 0.f, xa1 = 0.f, xb1 = 0.f;
    if (isL1) { xa0 = xg0[ga]; xb0 = xg0[gb]; xa1 = xg1[ga]; xb1 = xg1[gb]; }

    #define COMBINE2(pa0, pb0, pa1, pb1, d0, d1) do {                          \
        float va0_ = sigf(pa0);                                                \
        float va1_ = sigf(pa1);                                                \
        float vb0_ = half ? sigf(pb0) : tanhfast(pb0);                         \
        float vb1_ = half ? sigf(pb1) : tanhfast(pb1);                         \
        float pay0_ = va0_ * vb0_;                                             \
        float pay1_ = va1_ * vb1_;                                             \
        float got0_ = __shfl_xor_sync(0xffffffffu, pay0_, 1);                  \
        float got1_ = __shfl_xor_sync(0xffffffffu, pay1_, 1);                  \
        if (half) {                                                            \
            cst0 = fmaf(va0_, cst0, got0_);                                    \
            cst1 = fmaf(va1_, cst1, got1_);                                    \
            (d0)[cell] = vb0_ * tanhfast(cst0);                                \
            (d1)[cell] = vb1_ * tanhfast(cst1);                                \
        }                                                                      \
    } while (0)

    #define GEMV_L(buf0, buf1, A00, A01, B00, B01, A10, A11, B10, B11) do {    \
        _Pragma("unroll")                                                      \
        for (int i = 0; i < 8; ++i) {                                          \
            float4 h0 = ((const float4*)(buf0))[i];                            \
            float4 h1 = ((const float4*)(buf1))[i];                            \
            A00 = fmaf(h0.x, wLa[i].x, A00); A01 = fmaf(h0.y, wLa[i].y, A01);  \
            A00 = fmaf(h0.z, wLa[i].z, A00); A01 = fmaf(h0.w, wLa[i].w, A01);  \
            B00 = fmaf(h0.x, wLb[i].x, B00); B01 = fmaf(h0.y, wLb[i].y, B01);  \
            B00 = fmaf(h0.z, wLb[i].z, B00); B01 = fmaf(h0.w, wLb[i].w, B01);  \
            A10 = fmaf(h1.x, wLa[i].x, A10); A11 = fmaf(h1.y, wLa[i].y, A11);  \
            A10 = fmaf(h1.z, wLa[i].z, A10); A11 = fmaf(h1.w, wLa[i].w, A11);  \
            B10 = fmaf(h1.x, wLb[i].x, B10); B11 = fmaf(h1.y, wLb[i].y, B11);  \
            B10 = fmaf(h1.z, wLb[i].z, B10); B11 = fmaf(h1.w, wLb[i].w, B11);  \
        }                                                                      \
    } while (0)

    #define GEMV_S(buf0, buf1, A00, A01, B00, B01, A10, A11, B10, B11) do {    \
        _Pragma("unroll")                                                      \
        for (int i = 0; i < 4; ++i) {                                          \
            float4 h0 = ((const float4*)(buf0))[i];                            \
            float4 h1 = ((const float4*)(buf1))[i];                            \
            A00 = fmaf(h0.x, wSa[i].x, A00); A01 = fmaf(h0.y, wSa[i].y, A01);  \
            A00 = fmaf(h0.z, wSa[i].z, A00); A01 = fmaf(h0.w, wSa[i].w, A01);  \
            B00 = fmaf(h0.x, wSb[i].x, B00); B01 = fmaf(h0.y, wSb[i].y, B01);  \
            B00 = fmaf(h0.z, wSb[i].z, B00); B01 = fmaf(h0.w, wSb[i].w, B01);  \
            A10 = fmaf(h1.x, wSa[i].x, A10); A11 = fmaf(h1.y, wSa[i].y, A11);  \
            A10 = fmaf(h1.z, wSa[i].z, A10); A11 = fmaf(h1.w, wSa[i].w, A11);  \
            B10 = fmaf(h1.x, wSb[i].x, B10); B11 = fmaf(h1.y, wSb[i].y, B11);  \
            B10 = fmaf(h1.z, wSb[i].z, B10); B11 = fmaf(h1.w, wSb[i].w, B11);  \
        }                                                                      \
    } while (0)

    for (int tau = 0; tau < TT + 2; ++tau) {
        int wp = tau & 1, rp = wp ^ 1;

        if (isL1) {
            if (tau < TT) {
                float a00 = xa0, a01 = 0.f, b00 = xb0, b01 = 0.f;
                float a10 = xa1, a11 = 0.f, b10 = xb1, b11 = 0.f;
                GEMV_L(h1s[0][rp], h1s[1][rp], a00, a01, b00, b01, a10, a11, b10, b11);
                if (tau + 1 < TT) {
                    size_t off = (size_t)(tau + 1) * D1;
                    xa0 = xg0[off + ga]; xb0 = xg0[off + gb];
                    xa1 = xg1[off + ga]; xb1 = xg1[off + gb];
                }
                COMBINE2(a00 + a01, b00 + b01, a10 + a11, b10 + b11,
                         h1s[0][wp], h1s[1][wp]);
            }
        } else if (isL2) {
            if (tau >= 1 && tau <= TT) {
                float a00 = biasa, a01 = 0.f, b00 = biasb, b01 = 0.f;
                float a10 = biasa, a11 = 0.f, b10 = biasb, b11 = 0.f;
                GEMV_L(h1s[0][rp], h1s[1][rp], a00, a01, b00, b01, a10, a11, b10, b11);
                GEMV_S(h2s[0][rp], h2s[1][rp], a00, a01, b00, b01, a10, a11, b10, b11);
                COMBINE2(a00 + a01, b00 + b01, a10 + a11, b10 + b11,
                         h2s[0][wp], h2s[1][wp]);
            }
        } else {
            if (tau >= 2) {
                float a00 = biasa, a01 = 0.f, b00 = biasb, b01 = 0.f;
                float a10 = biasa, a11 = 0.f, b10 = biasb, b11 = 0.f;
                GEMV_S(h2s[0][rp], h2s[1][rp], a00, a01, b00, b01, a10, a11, b10, b11);
                GEMV_L(h3s[0][rp], h3s[1][rp], a00, a01, b00, b01, a10, a11, b10, b11);
                COMBINE2(a00 + a01, b00 + b01, a10 + a11, b10 + b11,
                         h3s[0][wp], h3s[1][wp]);
            }
        }
        __syncthreads();
    }

    if (tid < 32) {
        int fp = (TT + 1) & 1;
        out[bb * 32 + tid]       = h3s[0][fp][tid];
        out[(bb + 1) * 32 + tid] = h3s[1][fp][tid];
    }
}

// ---------------- launch ----------------
extern "C" void kernel_launch(void* const* d_in, const int* in_sizes, int n_in,
                              void* d_out, int out_size) {
    const float* x      = (const float*)d_in[0];
    const float* conv_w = (const float*)d_in[1];
    const float* conv_b = (const float*)d_in[2];
    const float* Wih1   = (const float*)d_in[3];
    const float* Whh1   = (const float*)d_in[4];
    const float* bih1   = (const float*)d_in[5];
    const float* bhh1   = (const float*)d_in[6];
    const float* Wih2   = (const float*)d_in[7];
    const float* Whh2   = (const float*)d_in[8];
    const float* bih2   = (const float*)d_in[9];
    const float* bhh2   = (const float*)d_in[10];
    const float* Wih3   = (const float*)d_in[11];
    const float* Whh3   = (const float*)d_in[12];
    const float* bih3   = (const float*)d_in[13];
    const float* bhh3   = (const float*)d_in[14];
    float* out = (float*)d_out;

    const int conv_smem = 2 * 136 * 68 * 4;   // 73984 B
    const int xg_smem   = 2 * 128 * 68 * 4;   // 69632 B
    cudaFuncSetAttribute(conv_mma_kernel, cudaFuncAttributeMaxDynamicSharedMemorySize, conv_smem);
    cudaFuncSetAttribute(xg_mma_kernel,   cudaFuncAttributeMaxDynamicSharedMemorySize, xg_smem);

    prep_kernel<<<160, 256>>>(conv_w, Wih1);
    conv_mma_kernel<<<dim3(8, B), 256, conv_smem>>>(x, conv_b);
    xg_mma_kernel<<<dim3(8, B), 256, xg_smem>>>(bih1, bhh1);
    lstm_kernel<<<B / 2, 160>>>(Whh1, Wih2, Whh2, bih2, bhh2,
                                Wih3, Whh3, bih3, bhh3, out);
}